// round 15
// baseline (speedup 1.0000x reference)
#include <cuda_runtime.h>
#include <cstddef>
#include <cstdint>

#define NPTS 100000
#define KNN 20
#define NEGINF -3.4e38f
#define NEGPK 0xFF80FF80u

__device__ __forceinline__ float lrelu(float x) { return fmaxf(x, 0.2f * x); }
__device__ __forceinline__ uint32_t packbf(float lo, float hi) {
    uint32_t r;
    asm("cvt.rn.bf16x2.f32 %0, %1, %2;" : "=r"(r) : "f"(hi), "f"(lo));
    return r;
}
__device__ __forceinline__ uint32_t vmax2(uint32_t a, uint32_t b) {
    uint32_t r;
    asm("max.bf16x2 %0, %1, %2;" : "=r"(r) : "r"(a), "r"(b));
    return r;
}
__device__ __forceinline__ void mma16(float* d, const uint4& a, uint32_t b0, uint32_t b1) {
    asm volatile(
        "mma.sync.aligned.m16n8k16.row.col.f32.bf16.bf16.f32 "
        "{%0,%1,%2,%3}, {%4,%5,%6,%7}, {%8,%9}, {%0,%1,%2,%3};"
        : "+f"(d[0]), "+f"(d[1]), "+f"(d[2]), "+f"(d[3])
        : "r"(a.x), "r"(a.y), "r"(a.z), "r"(a.w), "r"(b0), "r"(b1));
}
#define BAR_MG(id) asm volatile("bar.sync %0, 256;" ::"r"(id) : "memory")
__device__ __forceinline__ void cpasync4(uint32_t smaddr, const void* gaddr) {
    asm volatile("cp.async.ca.shared.global [%0], [%1], 4;" ::"r"(smaddr), "l"(gaddr)
                 : "memory");
}
#define CP_COMMIT() asm volatile("cp.async.commit_group;" ::: "memory")
#define CP_WAIT(n) asm volatile("cp.async.wait_group %0;" ::"n"(n) : "memory")

// ======================= device scratch ================================================
__device__ int      g_idx64;
__device__ float    g_w1T[3 * 3 * 64];
__device__ uint32_t g_w2b[3 * 4096];
__device__ uint32_t g_w3b[3 * 16384];
__device__ uint32_t g_sw1b[32 * 48 * 64];
__device__ uint32_t g_sw2b[16 * 16 * 64];
__device__ uint32_t g_sw3b[8 * 8 * 64];
__device__ float    g_sw4T[64 * 32];
__device__ uint32_t g_featsb[(size_t)NPTS * 384];

// prep: weight reshapes + idx-dtype detection (block 0)
__global__ void prep_kernel(const float* __restrict__ pw1, const float* __restrict__ pw2,
                            const float* __restrict__ pw3, const float* __restrict__ sw1,
                            const float* __restrict__ sw2, const float* __restrict__ sw3,
                            const float* __restrict__ sw4,
                            const unsigned int* __restrict__ raw) {
    const int tid = blockIdx.x * blockDim.x + threadIdx.x;
    const int stride = gridDim.x * blockDim.x;
    if (blockIdx.x == 0) {
        __shared__ int flag;
        if (threadIdx.x == 0) flag = 0;
        __syncthreads();
        if (raw[2 * threadIdx.x + 1] != 0u) atomicOr(&flag, 1);
        __syncthreads();
        if (threadIdx.x == 0) g_idx64 = (flag == 0) ? 1 : 0;
    }
    for (int i = tid; i < 3 * 3 * 64; i += stride) {
        int s = i / 192, r = i % 192, c = r / 64, d = r % 64;
        g_w1T[i] = pw1[s * 192 + d * 3 + c];
    }
    for (int i = tid; i < 3 * 128 * 32; i += stride) {
        int s = i / 4096, r = i % 4096, n = r >> 5, k2 = r & 31, k = k2 * 2;
        float v0 = pw2[s * 8192 + n * 64 + k];
        float v1 = pw2[s * 8192 + n * 64 + k + 1];
        int idx = (((n >> 3) * 4 + (k2 >> 3)) * 32 + (n & 7) * 4 + (k2 & 3)) * 2 +
                  ((k2 >> 2) & 1);
        g_w2b[s * 4096 + idx] = packbf(v0, v1);
    }
    for (int i = tid; i < 3 * 256 * 64; i += stride) {
        int s = i >> 14, r = i & 16383, n = r >> 6, k2 = r & 63, k = k2 * 2;
        float v0 = pw3[s * 32768 + n * 128 + k];
        float v1 = pw3[s * 32768 + n * 128 + k + 1];
        int ng = n >> 5, nq = (n >> 3) & 3, pair = nq >> 1, nqi = nq & 1;
        int ks = k2 >> 3, reg = (k2 >> 2) & 1, lane = (n & 7) * 4 + (k2 & 3);
        int idx = ((((ng * 8 + ks) * 2 + pair) * 32 + lane) * 4) + nqi * 2 + reg;
        g_w3b[s * 16384 + idx] = packbf(v0, v1);
    }
    for (int i = tid; i < 256 * 384; i += stride) {
        int n = i / 384, kp = i % 384;
        int ks = kp >> 3, k2 = kp & 7;
        int idx = ((n >> 3) * 48 + ks) * 64 + ((n & 7) * 4 + (k2 & 3)) * 2 + ((k2 >> 2) & 1);
        g_sw1b[idx] = packbf(sw1[n * 768 + 2 * kp], sw1[n * 768 + 2 * kp + 1]);
    }
    for (int i = tid; i < 128 * 128; i += stride) {
        int n = i >> 7, kp = i & 127;
        int ks = kp >> 3, k2 = kp & 7;
        int idx = ((n >> 3) * 16 + ks) * 64 + ((n & 7) * 4 + (k2 & 3)) * 2 + ((k2 >> 2) & 1);
        g_sw2b[idx] = packbf(sw2[n * 256 + 2 * kp], sw2[n * 256 + 2 * kp + 1]);
    }
    for (int i = tid; i < 64 * 64; i += stride) {
        int n = i >> 6, kp = i & 63;
        int ks = kp >> 3, k2 = kp & 7;
        int idx = ((n >> 3) * 8 + ks) * 64 + ((n & 7) * 4 + (k2 & 3)) * 2 + ((k2 >> 2) & 1);
        g_sw3b[idx] = packbf(sw3[n * 128 + 2 * kp], sw3[n * 128 + 2 * kp + 1]);
    }
    for (int i = tid; i < 64 * 32; i += stride) {
        int k = i >> 5, d = i & 31;
        g_sw4T[i] = sw4[d * 64 + k];
    }
}

// ======================= patch stage: 160-row supertile, decoupled mg halves ===========
#define PF_W3F  0        // 16384
#define PF_H2F  16384    // 10240
#define PF_STG  26624    // 16 warps * 320 u32
#define PF_H1F  35072    // 5120
#define PF_NB   40192    // 640
#define PF_W1   40832    // 192
#define PF_B1   41024    // 64
#define PF_TOT  41088
#define SMEM_PATCH (PF_TOT * 4)
#define TROWS 160

template <int SI>
__device__ __forceinline__ void patch_run(
    float* sm, int bid, int nblk,
    const float* __restrict__ points, const void* __restrict__ nbr,
    const float* __restrict__ pb1, const float* __restrict__ pb2,
    const float* __restrict__ pb3) {
    constexpr int S = (SI == 0) ? 5 : (SI == 1 ? 10 : 20);
    constexpr int PTS = TROWS / S;
    constexpr int NT = NPTS / PTS;

    uint32_t* smu = (uint32_t*)sm;
    const int t = threadIdx.x;
    const int w = t >> 5, lane = t & 31;
    const int ng = w & 7, mg = w >> 3;
    const int tl = t & 255;  // index within mg group
    const int is64 = g_idx64;

    {
        const uint4* src = (const uint4*)g_w3b + SI * 4096;
        uint4* dst = (uint4*)(smu + PF_W3F);
        for (int i = t; i < 4096; i += 512) dst[i] = src[i];
        for (int i = t; i < 192; i += 512) sm[PF_W1 + i] = g_w1T[SI * 192 + i];
        if (t < 64) sm[PF_B1 + t] = pb1[SI * 64 + t];
    }
    uint32_t bw2[2][4][2];
#pragma unroll
    for (int nl = 0; nl < 2; nl++)
#pragma unroll
        for (int ks = 0; ks < 4; ks++) {
            uint2 v = *(const uint2*)(g_w2b + SI * 4096 +
                                      (((2 * ng + nl) * 4 + ks) * 32 + lane) * 2);
            bw2[nl][ks][0] = v.x;
            bw2[nl][ks][1] = v.y;
        }
    float b2e[2], b2o[2];
#pragma unroll
    for (int nl = 0; nl < 2; nl++) {
        int n0 = ng * 16 + nl * 8 + (lane & 3) * 2;
        b2e[nl] = pb2[SI * 128 + n0];
        b2o[nl] = pb2[SI * 128 + n0 + 1];
    }
    const float b3v = pb3[SI * 256 + ng * 32 + 2 * (lane >> 1) + (lane & 1)];
    const float b3lo = pb3[SI * 256 + ng * 32 + 2 * (lane & 15)];
    const float b3hi = pb3[SI * 256 + ng * 32 + 2 * (lane & 15) + 1];

    // prologue gather (own half rows)
    if (tl < 80) {
        const int grow = mg * 80 + tl;
        const int p = bid * PTS + mg * (80 / S) + tl / S, j = tl % S;
        long long gi = is64 ? ((const long long*)nbr)[(size_t)p * KNN + j]
                            : (long long)((const int*)nbr)[p * KNN + j];
        const float* q = points + gi * 3;
        const float* c = points + (long long)p * 3;
        sm[PF_NB + grow * 4 + 0] = q[0] - c[0];
        sm[PF_NB + grow * 4 + 1] = q[1] - c[1];
        sm[PF_NB + grow * 4 + 2] = q[2] - c[2];
    }
    __syncthreads();
    // prologue L1 (own half: 80 rows x 32 pairs = 2560 items / 256 thr)
#pragma unroll
    for (int ii = 0; ii < 10; ii++) {
        int i = tl + ii * 256;
        int d2 = i & 31, rl = i >> 5, r = mg * 80 + rl, d = d2 * 2;
        float v0 = sm[PF_B1 + d] + sm[PF_NB + r * 4] * sm[PF_W1 + d] +
                   sm[PF_NB + r * 4 + 1] * sm[PF_W1 + 64 + d] +
                   sm[PF_NB + r * 4 + 2] * sm[PF_W1 + 128 + d];
        float v1 = sm[PF_B1 + d + 1] + sm[PF_NB + r * 4] * sm[PF_W1 + d + 1] +
                   sm[PF_NB + r * 4 + 1] * sm[PF_W1 + 64 + d + 1] +
                   sm[PF_NB + r * 4 + 2] * sm[PF_W1 + 128 + d + 1];
        smu[PF_H1F + ((r >> 4) * 4 + (d2 >> 3)) * 128 + ((r & 7) * 4 + (d2 & 3)) * 4 +
            (((r & 8) >> 3) | ((d2 & 4) >> 1))] = packbf(lrelu(v0), lrelu(v1));
    }
    __syncthreads();

    for (int tile = bid; tile < NT; tile += nblk) {
        const int pt0 = tile * PTS;
        const bool pf = (tl < 80) && (tile + nblk < NT);

        long long gi_n = 0;
        int pn = 0;
        if (pf) {
            pn = (tile + nblk) * PTS + mg * (80 / S) + tl / S;
            int j = tl % S;
            gi_n = is64 ? ((const long long*)nbr)[(size_t)pn * KNN + j]
                        : (long long)((const int*)nbr)[pn * KNN + j];
        }

        // ---- L2 mma ----
        float acc2[5][2][4];
#pragma unroll
        for (int im = 0; im < 5; im++)
#pragma unroll
            for (int nl = 0; nl < 2; nl++)
#pragma unroll
                for (int e = 0; e < 4; e++) acc2[im][nl][e] = 0.f;
        const uint4* h1u4 = (const uint4*)(smu + PF_H1F);
#pragma unroll
        for (int ks = 0; ks < 4; ks++)
#pragma unroll
            for (int im = 0; im < 5; im++) {
                int mta = mg * 5 + im;
                uint4 A = h1u4[(mta * 4 + ks) * 32 + lane];
                mma16(acc2[im][0], A, bw2[0][ks][0], bw2[0][ks][1]);
                mma16(acc2[im][1], A, bw2[1][ks][0], bw2[1][ks][1]);
            }
        // ---- L2 epilogue -> H2F ----
        {
            uint4* h2u4 = (uint4*)(smu + PF_H2F);
#pragma unroll
            for (int im = 0; im < 5; im++) {
                int mta = mg * 5 + im;
                uint4 v;
                v.x = packbf(lrelu(acc2[im][0][0] + b2e[0]), lrelu(acc2[im][0][1] + b2o[0]));
                v.y = packbf(lrelu(acc2[im][0][2] + b2e[0]), lrelu(acc2[im][0][3] + b2o[0]));
                v.z = packbf(lrelu(acc2[im][1][0] + b2e[1]), lrelu(acc2[im][1][1] + b2o[1]));
                v.w = packbf(lrelu(acc2[im][1][2] + b2e[1]), lrelu(acc2[im][1][3] + b2o[1]));
                h2u4[(mta * 8 + ng) * 32 + lane] = v;
            }
        }
        BAR_MG(1 + mg);  // own-half H2F ready

        float d0 = 0.f, d1 = 0.f, d2 = 0.f;
        if (pf) {
            const float* q = points + gi_n * 3;
            const float* c = points + (long long)pn * 3;
            d0 = q[0] - c[0];
            d1 = q[1] - c[1];
            d2 = q[2] - c[2];
        }

        // ---- L3 mma ----
        float acc3[5][4][4];
#pragma unroll
        for (int im = 0; im < 5; im++)
#pragma unroll
            for (int nq = 0; nq < 4; nq++)
#pragma unroll
                for (int e = 0; e < 4; e++) acc3[im][nq][e] = 0.f;
        const uint4* w3u4 = (const uint4*)(smu + PF_W3F);
        const uint4* h2u4 = (const uint4*)(smu + PF_H2F);
#pragma unroll
        for (int ks = 0; ks < 8; ks++) {
            int base = ((ng * 8 + ks) * 2) * 32 + lane;
            uint4 b01 = w3u4[base];
            uint4 b23 = w3u4[base + 32];
#pragma unroll
            for (int im = 0; im < 5; im++) {
                int mta = mg * 5 + im;
                uint4 A = h2u4[(mta * 8 + ks) * 32 + lane];
                mma16(acc3[im][0], A, b01.x, b01.y);
                mma16(acc3[im][1], A, b01.z, b01.w);
                mma16(acc3[im][2], A, b23.x, b23.y);
                mma16(acc3[im][3], A, b23.z, b23.w);
            }
        }

        // ---- staging + pooled max + feats write (warp/half private) ----
        {
            uint32_t* stg = smu + PF_STG + w * 320;
            if (S == 5) {
                float cur = NEGINF;
#pragma unroll
                for (int im = 0; im < 5; im++) {
                    __syncwarp();
#pragma unroll
                    for (int nq = 0; nq < 4; nq++) {
                        uint32_t lo = packbf(acc3[im][nq][0], acc3[im][nq][1]);
                        uint32_t hi = packbf(acc3[im][nq][2], acc3[im][nq][3]);
                        int cs = nq * 4 + (lane & 3);
                        stg[(lane >> 2) * 20 + cs] = lo;
                        stg[((lane >> 2) + 8) * 20 + cs] = hi;
                    }
                    __syncwarp();
#pragma unroll
                    for (int r = 0; r < 16; r++) {
                        uint32_t u = stg[r * 20 + (lane >> 1)];
                        float v = __uint_as_float((lane & 1) ? (u & 0xffff0000u) : (u << 16));
                        cur = fmaxf(cur, v);
                        if (((im * 16 + r + 1) % S) == 0) {
                            int pt = mg * (80 / S) + (im * 16 + r) / S;
                            float val = cur + b3v;
                            float oth = __shfl_xor_sync(0xffffffffu, val, 1);
                            if (!(lane & 1))
                                g_featsb[(size_t)(pt0 + pt) * 384 + SI * 128 + ng * 16 +
                                         (lane >> 1)] = packbf(val, oth);
                            cur = NEGINF;
                        }
                    }
                }
            } else {
                const int cp = lane & 15, rh = lane >> 4;
                uint32_t curp = NEGPK;
#pragma unroll
                for (int im = 0; im < 5; im++) {
                    __syncwarp();
#pragma unroll
                    for (int nq = 0; nq < 4; nq++) {
                        uint32_t lo = packbf(acc3[im][nq][0], acc3[im][nq][1]);
                        uint32_t hi = packbf(acc3[im][nq][2], acc3[im][nq][3]);
                        int cs = nq * 4 + (lane & 3);
                        stg[(lane >> 2) * 20 + cs] = lo;
                        stg[((lane >> 2) + 8) * 20 + cs] = hi;
                    }
                    __syncwarp();
#pragma unroll
                    for (int rr = 0; rr < 8; rr++) {
                        int r = 2 * rr + rh;
                        curp = vmax2(curp, stg[r * 20 + cp]);
                        if (((im * 16 + 2 * rr + 2) % S) == 0) {
                            uint32_t o = __shfl_xor_sync(0xffffffffu, curp, 16);
                            curp = vmax2(curp, o);
                            if (rh == 0) {
                                float lo = __uint_as_float(curp << 16) + b3lo;
                                float hi = __uint_as_float(curp & 0xffff0000u) + b3hi;
                                int grow = im * 16 + 2 * rr + 1;
                                int pt = mg * (80 / S) + grow / S;
                                g_featsb[(size_t)(pt0 + pt) * 384 + SI * 128 + ng * 16 + cp] =
                                    packbf(lo, hi);
                            }
                            curp = NEGPK;
                        }
                    }
                }
            }
        }
        if (pf) {
            const int grow = mg * 80 + tl;
            sm[PF_NB + grow * 4 + 0] = d0;
            sm[PF_NB + grow * 4 + 1] = d1;
            sm[PF_NB + grow * 4 + 2] = d2;
        }
        BAR_MG(1 + mg);  // own-half NB ready; own-half H2F reads done

        // ---- L1 for next tile (own half) ----
        if (tile + nblk < NT) {
#pragma unroll
            for (int ii = 0; ii < 10; ii++) {
                int i = tl + ii * 256;
                int dd2 = i & 31, rl = i >> 5, r = mg * 80 + rl, d = dd2 * 2;
                float v0 = sm[PF_B1 + d] + sm[PF_NB + r * 4] * sm[PF_W1 + d] +
                           sm[PF_NB + r * 4 + 1] * sm[PF_W1 + 64 + d] +
                           sm[PF_NB + r * 4 + 2] * sm[PF_W1 + 128 + d];
                float v1 = sm[PF_B1 + d + 1] + sm[PF_NB + r * 4] * sm[PF_W1 + d + 1] +
                           sm[PF_NB + r * 4 + 1] * sm[PF_W1 + 64 + d + 1] +
                           sm[PF_NB + r * 4 + 2] * sm[PF_W1 + 128 + d + 1];
                smu[PF_H1F + ((r >> 4) * 4 + (dd2 >> 3)) * 128 + ((r & 7) * 4 + (dd2 & 3)) * 4 +
                    (((r & 8) >> 3) | ((dd2 & 4) >> 1))] = packbf(lrelu(v0), lrelu(v1));
            }
        }
        BAR_MG(1 + mg);  // own-half H1F ready for next L2
    }
}

__global__ void __launch_bounds__(512) patch_all_kernel(
    const float* __restrict__ points, const void* __restrict__ nbr,
    const float* __restrict__ pb1, const float* __restrict__ pb2,
    const float* __restrict__ pb3) {
    extern __shared__ float sm[];
    int b = blockIdx.x;
    if (b < 42)       patch_run<0>(sm, b,       42,  points, nbr, pb1, pb2, pb3);
    else if (b < 127) patch_run<1>(sm, b - 42,  85,  points, nbr, pb1, pb2, pb3);
    else              patch_run<2>(sm, b - 127, 169, points, nbr, pb1, pb2, pb3);
}

// ======================= shared MLP: bf16 mma + cp.async double buffer =================
#define MF_A   0        // buf0 (4096 u32); buf1 at 4096 (front of H1F region)
#define MF_H1F 4096
#define MF_H3  4096
#define MF_H4  8256
#define MF_SB1 12288
#define MF_SB2 12544
#define MF_SB3 12672
#define MF_SB4 12736
#define MF_W5  12768
#define MF_W4  12800
#define MF_TOT 14848
#define SMEM_MLP (MF_TOT * 4)

__global__ void __launch_bounds__(256, 2) mlp_kernel(
    const float* __restrict__ sb1, const float* __restrict__ sb2,
    const float* __restrict__ sb3, const float* __restrict__ sb4,
    const float* __restrict__ sw5, const float* __restrict__ sb5,
    float* __restrict__ out) {
    extern __shared__ float sm[];
    uint32_t* smu = (uint32_t*)sm;
    const int t = threadIdx.x;
    const int w = t >> 5, lane = t & 31;
    const int pt0 = blockIdx.x * 64;
    const uint32_t smbase = (uint32_t)__cvta_generic_to_shared(smu);

    for (int i = t; i < 2048; i += 256) sm[MF_W4 + i] = g_sw4T[i];
    if (t < 256) sm[MF_SB1 + t] = sb1[t];
    if (t < 128) sm[MF_SB2 + t] = sb2[t];
    if (t < 64) sm[MF_SB3 + t] = sb3[t];
    if (t < 32) {
        sm[MF_SB4 + t] = sb4[t];
        sm[MF_W5 + t] = sw5[t];
    }

    // issue chunk copies via cp.async (16 x 4B per thread)
    auto issue_chunk = [&](int c, int buf) {
#pragma unroll
        for (int ii = 0; ii < 16; ii++) {
            int i = ii * 256 + t;
            int reg = i & 3, ln = (i >> 2) & 31, ksl = (i >> 7) & 7, mt = i >> 10;
            int row = (ln >> 2) + 8 * (reg & 1);
            int kpair = ksl * 8 + (ln & 3) + 4 * (reg >> 1);
            int p = pt0 + mt * 16 + row;
            if (p >= NPTS) p = NPTS - 1;
            cpasync4(smbase + (buf * 4096 + i) * 4,
                     g_featsb + (size_t)p * 384 + c * 64 + kpair);
        }
        CP_COMMIT();
    };
    issue_chunk(0, 0);

    float acc1[4][4][4];
#pragma unroll
    for (int mt = 0; mt < 4; mt++)
#pragma unroll
        for (int nt = 0; nt < 4; nt++)
#pragma unroll
            for (int e = 0; e < 4; e++) acc1[mt][nt][e] = 0.f;

    for (int c = 0; c < 6; c++) {
        if (c < 5) {
            issue_chunk(c + 1, (c + 1) & 1);
            CP_WAIT(1);
        } else {
            CP_WAIT(0);
        }
        __syncthreads();  // chunk c visible to all
        const uint2* w1b = (const uint2*)g_sw1b;
        const uint4* au4 = (const uint4*)(smu + ((c & 1) ? 4096 : 0));
#pragma unroll
        for (int ksl = 0; ksl < 8; ksl++) {
            uint2 b[4];
#pragma unroll
            for (int nt = 0; nt < 4; nt++)
                b[nt] = w1b[((w * 4 + nt) * 48 + c * 8 + ksl) * 32 + lane];
#pragma unroll
            for (int mt = 0; mt < 4; mt++) {
                uint4 A = au4[(mt * 8 + ksl) * 32 + lane];
#pragma unroll
                for (int nt = 0; nt < 4; nt++) mma16(acc1[mt][nt], A, b[nt].x, b[nt].y);
            }
        }
        __syncthreads();  // all done reading chunk c (its buffer is re-written at c+2)
    }
    // L1 epilogue -> H1F bf16 A-frags
#pragma unroll
    for (int mt = 0; mt < 4; mt++)
#pragma unroll
        for (int nt = 0; nt < 4; nt++) {
            int n0 = (w * 4 + nt) * 8 + (lane & 3) * 2;
            float be = sm[MF_SB1 + n0], bo = sm[MF_SB1 + n0 + 1];
            uint32_t lo = packbf(lrelu(acc1[mt][nt][0] + be), lrelu(acc1[mt][nt][1] + bo));
            uint32_t hi = packbf(lrelu(acc1[mt][nt][2] + be), lrelu(acc1[mt][nt][3] + bo));
            int kp = (w * 4 + nt) * 4 + (lane & 3);
            int ks = kp >> 3, kpf = kp & 7;
            int lanep = (lane >> 2) * 4 + (kpf & 3);
            int r0 = (kpf & 4) >> 1;
            *(uint2*)(smu + MF_H1F + (mt * 16 + ks) * 128 + lanep * 4 + r0) =
                make_uint2(lo, hi);
        }
    __syncthreads();

    float acc2[4][2][4];
#pragma unroll
    for (int mt = 0; mt < 4; mt++)
#pragma unroll
        for (int j = 0; j < 2; j++)
#pragma unroll
            for (int e = 0; e < 4; e++) acc2[mt][j][e] = 0.f;
    {
        const uint2* w2b = (const uint2*)g_sw2b;
        const uint4* au4 = (const uint4*)(smu + MF_H1F);
#pragma unroll 4
        for (int ks = 0; ks < 16; ks++) {
            uint2 b0 = w2b[(w * 16 + ks) * 32 + lane];
            uint2 b1 = w2b[((w + 8) * 16 + ks) * 32 + lane];
#pragma unroll
            for (int mt = 0; mt < 4; mt++) {
                uint4 A = au4[(mt * 16 + ks) * 32 + lane];
                mma16(acc2[mt][0], A, b0.x, b0.y);
                mma16(acc2[mt][1], A, b1.x, b1.y);
            }
        }
    }
    __syncthreads();
#pragma unroll
    for (int mt = 0; mt < 4; mt++)
#pragma unroll
        for (int j = 0; j < 2; j++) {
            int n0 = (w + j * 8) * 8 + (lane & 3) * 2;
            float be = sm[MF_SB2 + n0], bo = sm[MF_SB2 + n0 + 1];
            uint32_t lo = packbf(lrelu(acc2[mt][j][0] + be), lrelu(acc2[mt][j][1] + bo));
            uint32_t hi = packbf(lrelu(acc2[mt][j][2] + be), lrelu(acc2[mt][j][3] + bo));
            int kp = (w + j * 8) * 4 + (lane & 3);
            int ks = kp >> 3, kpf = kp & 7;
            int lanep = (lane >> 2) * 4 + (kpf & 3);
            int r0 = (kpf & 4) >> 1;
            *(uint2*)(smu + MF_A + (mt * 8 + ks) * 128 + lanep * 4 + r0) = make_uint2(lo, hi);
        }
    __syncthreads();

    float acc3[4][4];
#pragma unroll
    for (int mt = 0; mt < 4; mt++)
#pragma unroll
        for (int e = 0; e < 4; e++) acc3[mt][e] = 0.f;
    {
        const uint2* w3b = (const uint2*)g_sw3b;
        const uint4* au4 = (const uint4*)(smu + MF_A);
#pragma unroll
        for (int ks = 0; ks < 8; ks++) {
            uint2 b = w3b[(w * 8 + ks) * 32 + lane];
#pragma unroll
            for (int mt = 0; mt < 4; mt++) {
                uint4 A = au4[(mt * 8 + ks) * 32 + lane];
                mma16(acc3[mt], A, b.x, b.y);
            }
        }
    }
    __syncthreads();
#pragma unroll
    for (int mt = 0; mt < 4; mt++)
#pragma unroll
        for (int e = 0; e < 4; e++) {
            int m = mt * 16 + (lane >> 2) + ((e >> 1) << 3);
            int n = w * 8 + ((lane & 3) << 1) + (e & 1);
            sm[MF_H3 + m * 65 + n] = lrelu(acc3[mt][e] + sm[MF_SB3 + n]);
        }
    __syncthreads();

#pragma unroll
    for (int ii = 0; ii < 8; ii++) {
        int idx = t + ii * 256;
        int m = idx >> 5, d = idx & 31;
        float a = sm[MF_SB4 + d];
#pragma unroll 8
        for (int k = 0; k < 64; k++) a += sm[MF_H3 + m * 65 + k] * sm[MF_W4 + k * 32 + d];
        sm[MF_H4 + m * 33 + d] = lrelu(a);
    }
    __syncthreads();

    if (t < 64) {
        float s = __ldg(sb5);
#pragma unroll
        for (int k = 0; k < 32; k++) s += sm[MF_H4 + t * 33 + k] * sm[MF_W5 + k];
        int p = pt0 + t;
        if (p < NPTS) out[p] = s;
    }
}

// ======================= launch ========================================================
extern "C" void kernel_launch(void* const* d_in, const int* in_sizes, int n_in,
                              void* d_out, int out_size) {
    (void)out_size;
    const int want[18] = {300000, 2000000, 576, 192, 24576, 384, 98304, 768,
                          196608, 256,    32768, 128, 8192, 64,  2048,  32, 32, 1};
    const void* ptr[18] = {};
    {
        int used[64] = {};
        for (int w = 0; w < 18; w++) {
            for (int i = 0; i < n_in && i < 64; i++) {
                if (!used[i] && in_sizes[i] == want[w]) {
                    ptr[w] = d_in[i];
                    used[i] = 1;
                    break;
                }
            }
        }
        for (int w = 0; w < 18; w++)
            if (!ptr[w] && w < n_in) ptr[w] = d_in[w];
    }

    const float* points = (const float*)ptr[0];
    const void*  nbr    = ptr[1];
    const float* pw1 = (const float*)ptr[2];
    const float* pb1 = (const float*)ptr[3];
    const float* pw2 = (const float*)ptr[4];
    const float* pb2 = (const float*)ptr[5];
    const float* pw3 = (const float*)ptr[6];
    const float* pb3 = (const float*)ptr[7];
    const float* sw1 = (const float*)ptr[8];
    const float* sb1 = (const float*)ptr[9];
    const float* sw2 = (const float*)ptr[10];
    const float* sb2 = (const float*)ptr[11];
    const float* sw3 = (const float*)ptr[12];
    const float* sb3 = (const float*)ptr[13];
    const float* sw4 = (const float*)ptr[14];
    const float* sb4 = (const float*)ptr[15];
    const float* sw5 = (const float*)ptr[16];
    const float* sb5 = (const float*)ptr[17];

    cudaFuncSetAttribute(patch_all_kernel, cudaFuncAttributeMaxDynamicSharedMemorySize,
                         SMEM_PATCH);
    cudaFuncSetAttribute(mlp_kernel, cudaFuncAttributeMaxDynamicSharedMemorySize, SMEM_MLP);

    prep_kernel<<<128, 256>>>(pw1, pw2, pw3, sw1, sw2, sw3, sw4,
                              (const unsigned int*)nbr);
    patch_all_kernel<<<296, 512, SMEM_PATCH>>>(points, nbr, pb1, pb2, pb3);
    mlp_kernel<<<(NPTS + 63) / 64, 256, SMEM_MLP>>>(sb1, sb2, sb3, sb4, sw5, sb5,
                                                    (float*)d_out);
}

// round 16
// speedup vs baseline: 1.0831x; 1.0831x over previous
#include <cuda_runtime.h>
#include <cstddef>
#include <cstdint>

#define NPTS 100000
#define KNN 20
#define NEGINF -3.4e38f
#define NEGPK 0xFF80FF80u

__device__ __forceinline__ float lrelu(float x) { return fmaxf(x, 0.2f * x); }
__device__ __forceinline__ uint32_t packbf(float lo, float hi) {
    uint32_t r;
    asm("cvt.rn.bf16x2.f32 %0, %1, %2;" : "=r"(r) : "f"(hi), "f"(lo));
    return r;
}
__device__ __forceinline__ uint32_t vmax2(uint32_t a, uint32_t b) {
    uint32_t r;
    asm("max.bf16x2 %0, %1, %2;" : "=r"(r) : "r"(a), "r"(b));
    return r;
}
__device__ __forceinline__ void mma16(float* d, const uint4& a, uint32_t b0, uint32_t b1) {
    asm volatile(
        "mma.sync.aligned.m16n8k16.row.col.f32.bf16.bf16.f32 "
        "{%0,%1,%2,%3}, {%4,%5,%6,%7}, {%8,%9}, {%0,%1,%2,%3};"
        : "+f"(d[0]), "+f"(d[1]), "+f"(d[2]), "+f"(d[3])
        : "r"(a.x), "r"(a.y), "r"(a.z), "r"(a.w), "r"(b0), "r"(b1));
}
#define BAR_MG(id) asm volatile("bar.sync %0, 256;" ::"r"(id) : "memory")

// ======================= device scratch ================================================
__device__ int      g_idx64;
__device__ float    g_w1T[3 * 3 * 64];
__device__ uint32_t g_w2b[3 * 4096];
__device__ uint32_t g_w3b[3 * 16384];
__device__ uint32_t g_sw1b[32 * 48 * 64];
__device__ uint32_t g_sw2b[16 * 16 * 64];
__device__ uint32_t g_sw3b[8 * 8 * 64];
__device__ float    g_sw4T[64 * 32];
__device__ uint32_t g_featsb[(size_t)NPTS * 384];

// prep: weight reshapes + idx-dtype detection (block 0)
__global__ void prep_kernel(const float* __restrict__ pw1, const float* __restrict__ pw2,
                            const float* __restrict__ pw3, const float* __restrict__ sw1,
                            const float* __restrict__ sw2, const float* __restrict__ sw3,
                            const float* __restrict__ sw4,
                            const unsigned int* __restrict__ raw) {
    const int tid = blockIdx.x * blockDim.x + threadIdx.x;
    const int stride = gridDim.x * blockDim.x;
    if (blockIdx.x == 0) {
        __shared__ int flag;
        if (threadIdx.x == 0) flag = 0;
        __syncthreads();
        if (raw[2 * threadIdx.x + 1] != 0u) atomicOr(&flag, 1);
        __syncthreads();
        if (threadIdx.x == 0) g_idx64 = (flag == 0) ? 1 : 0;
    }
    for (int i = tid; i < 3 * 3 * 64; i += stride) {
        int s = i / 192, r = i % 192, c = r / 64, d = r % 64;
        g_w1T[i] = pw1[s * 192 + d * 3 + c];
    }
    for (int i = tid; i < 3 * 128 * 32; i += stride) {
        int s = i / 4096, r = i % 4096, n = r >> 5, k2 = r & 31, k = k2 * 2;
        float v0 = pw2[s * 8192 + n * 64 + k];
        float v1 = pw2[s * 8192 + n * 64 + k + 1];
        int idx = (((n >> 3) * 4 + (k2 >> 3)) * 32 + (n & 7) * 4 + (k2 & 3)) * 2 +
                  ((k2 >> 2) & 1);
        g_w2b[s * 4096 + idx] = packbf(v0, v1);
    }
    for (int i = tid; i < 3 * 256 * 64; i += stride) {
        int s = i >> 14, r = i & 16383, n = r >> 6, k2 = r & 63, k = k2 * 2;
        float v0 = pw3[s * 32768 + n * 128 + k];
        float v1 = pw3[s * 32768 + n * 128 + k + 1];
        int ng = n >> 5, nq = (n >> 3) & 3, pair = nq >> 1, nqi = nq & 1;
        int ks = k2 >> 3, reg = (k2 >> 2) & 1, lane = (n & 7) * 4 + (k2 & 3);
        int idx = ((((ng * 8 + ks) * 2 + pair) * 32 + lane) * 4) + nqi * 2 + reg;
        g_w3b[s * 16384 + idx] = packbf(v0, v1);
    }
    for (int i = tid; i < 256 * 384; i += stride) {
        int n = i / 384, kp = i % 384;
        int ks = kp >> 3, k2 = kp & 7;
        int idx = ((n >> 3) * 48 + ks) * 64 + ((n & 7) * 4 + (k2 & 3)) * 2 + ((k2 >> 2) & 1);
        g_sw1b[idx] = packbf(sw1[n * 768 + 2 * kp], sw1[n * 768 + 2 * kp + 1]);
    }
    for (int i = tid; i < 128 * 128; i += stride) {
        int n = i >> 7, kp = i & 127;
        int ks = kp >> 3, k2 = kp & 7;
        int idx = ((n >> 3) * 16 + ks) * 64 + ((n & 7) * 4 + (k2 & 3)) * 2 + ((k2 >> 2) & 1);
        g_sw2b[idx] = packbf(sw2[n * 256 + 2 * kp], sw2[n * 256 + 2 * kp + 1]);
    }
    for (int i = tid; i < 64 * 64; i += stride) {
        int n = i >> 6, kp = i & 63;
        int ks = kp >> 3, k2 = kp & 7;
        int idx = ((n >> 3) * 8 + ks) * 64 + ((n & 7) * 4 + (k2 & 3)) * 2 + ((k2 >> 2) & 1);
        g_sw3b[idx] = packbf(sw3[n * 128 + 2 * kp], sw3[n * 128 + 2 * kp + 1]);
    }
    for (int i = tid; i < 64 * 32; i += stride) {
        int k = i >> 5, d = i & 31;
        g_sw4T[i] = sw4[d * 64 + k];
    }
}

// ======================= patch stage: 160-row supertile (R14 proven) ===================
#define PF_W3F  0        // 16384
#define PF_H2F  16384    // 10240
#define PF_STG  26624    // 16 warps * 320 u32
#define PF_H1F  35072    // 5120
#define PF_NB   40192    // 640
#define PF_W1   40832    // 192
#define PF_B1   41024    // 64
#define PF_TOT  41088
#define SMEM_PATCH (PF_TOT * 4)
#define TROWS 160

template <int SI>
__device__ __forceinline__ void patch_run(
    float* sm, int bid, int nblk,
    const float* __restrict__ points, const void* __restrict__ nbr,
    const float* __restrict__ pb1, const float* __restrict__ pb2,
    const float* __restrict__ pb3) {
    constexpr int S = (SI == 0) ? 5 : (SI == 1 ? 10 : 20);
    constexpr int PTS = TROWS / S;
    constexpr int NT = NPTS / PTS;

    uint32_t* smu = (uint32_t*)sm;
    const int t = threadIdx.x;
    const int w = t >> 5, lane = t & 31;
    const int ng = w & 7, mg = w >> 3;
    const int is64 = g_idx64;

    {
        const uint4* src = (const uint4*)g_w3b + SI * 4096;
        uint4* dst = (uint4*)(smu + PF_W3F);
        for (int i = t; i < 4096; i += 512) dst[i] = src[i];
        for (int i = t; i < 192; i += 512) sm[PF_W1 + i] = g_w1T[SI * 192 + i];
        if (t < 64) sm[PF_B1 + t] = pb1[SI * 64 + t];
    }
    uint32_t bw2[2][4][2];
#pragma unroll
    for (int nl = 0; nl < 2; nl++)
#pragma unroll
        for (int ks = 0; ks < 4; ks++) {
            uint2 v = *(const uint2*)(g_w2b + SI * 4096 +
                                      (((2 * ng + nl) * 4 + ks) * 32 + lane) * 2);
            bw2[nl][ks][0] = v.x;
            bw2[nl][ks][1] = v.y;
        }
    float b2e[2], b2o[2];
#pragma unroll
    for (int nl = 0; nl < 2; nl++) {
        int n0 = ng * 16 + nl * 8 + (lane & 3) * 2;
        b2e[nl] = pb2[SI * 128 + n0];
        b2o[nl] = pb2[SI * 128 + n0 + 1];
    }
    const float b3v = pb3[SI * 256 + ng * 32 + 2 * (lane >> 1) + (lane & 1)];
    const float b3lo = pb3[SI * 256 + ng * 32 + 2 * (lane & 15)];
    const float b3hi = pb3[SI * 256 + ng * 32 + 2 * (lane & 15) + 1];

    if (t < TROWS) {
        const int p = bid * PTS + t / S, j = t % S;
        long long gi = is64 ? ((const long long*)nbr)[(size_t)p * KNN + j]
                            : (long long)((const int*)nbr)[p * KNN + j];
        const float* q = points + gi * 3;
        const float* c = points + (long long)p * 3;
        sm[PF_NB + t * 4 + 0] = q[0] - c[0];
        sm[PF_NB + t * 4 + 1] = q[1] - c[1];
        sm[PF_NB + t * 4 + 2] = q[2] - c[2];
    }
    __syncthreads();
#pragma unroll
    for (int ii = 0; ii < 10; ii++) {
        int i = t + ii * 512;
        int d2 = i & 31, r = i >> 5, d = d2 * 2;
        float v0 = sm[PF_B1 + d] + sm[PF_NB + r * 4] * sm[PF_W1 + d] +
                   sm[PF_NB + r * 4 + 1] * sm[PF_W1 + 64 + d] +
                   sm[PF_NB + r * 4 + 2] * sm[PF_W1 + 128 + d];
        float v1 = sm[PF_B1 + d + 1] + sm[PF_NB + r * 4] * sm[PF_W1 + d + 1] +
                   sm[PF_NB + r * 4 + 1] * sm[PF_W1 + 64 + d + 1] +
                   sm[PF_NB + r * 4 + 2] * sm[PF_W1 + 128 + d + 1];
        smu[PF_H1F + ((r >> 4) * 4 + (d2 >> 3)) * 128 + ((r & 7) * 4 + (d2 & 3)) * 4 +
            (((r & 8) >> 3) | ((d2 & 4) >> 1))] = packbf(lrelu(v0), lrelu(v1));
    }
    __syncthreads();

    for (int tile = bid; tile < NT; tile += nblk) {
        const int pt0 = tile * PTS;
        const bool pf = (t < TROWS) && (tile + nblk < NT);

        long long gi_n = 0;
        int pn = 0;
        if (pf) {
            pn = (tile + nblk) * PTS + t / S;
            int j = t % S;
            gi_n = is64 ? ((const long long*)nbr)[(size_t)pn * KNN + j]
                        : (long long)((const int*)nbr)[pn * KNN + j];
        }

        // ---- L2 mma ----
        float acc2[5][2][4];
#pragma unroll
        for (int im = 0; im < 5; im++)
#pragma unroll
            for (int nl = 0; nl < 2; nl++)
#pragma unroll
                for (int e = 0; e < 4; e++) acc2[im][nl][e] = 0.f;
        const uint4* h1u4 = (const uint4*)(smu + PF_H1F);
#pragma unroll
        for (int ks = 0; ks < 4; ks++)
#pragma unroll
            for (int im = 0; im < 5; im++) {
                int mta = mg * 5 + im;
                uint4 A = h1u4[(mta * 4 + ks) * 32 + lane];
                mma16(acc2[im][0], A, bw2[0][ks][0], bw2[0][ks][1]);
                mma16(acc2[im][1], A, bw2[1][ks][0], bw2[1][ks][1]);
            }
        // ---- L2 epilogue -> H2F ----
        {
            uint4* h2u4 = (uint4*)(smu + PF_H2F);
#pragma unroll
            for (int im = 0; im < 5; im++) {
                int mta = mg * 5 + im;
                uint4 v;
                v.x = packbf(lrelu(acc2[im][0][0] + b2e[0]), lrelu(acc2[im][0][1] + b2o[0]));
                v.y = packbf(lrelu(acc2[im][0][2] + b2e[0]), lrelu(acc2[im][0][3] + b2o[0]));
                v.z = packbf(lrelu(acc2[im][1][0] + b2e[1]), lrelu(acc2[im][1][1] + b2o[1]));
                v.w = packbf(lrelu(acc2[im][1][2] + b2e[1]), lrelu(acc2[im][1][3] + b2o[1]));
                h2u4[(mta * 8 + ng) * 32 + lane] = v;
            }
        }
        BAR_MG(1 + mg);

        float d0 = 0.f, d1 = 0.f, d2 = 0.f;
        if (pf) {
            const float* q = points + gi_n * 3;
            const float* c = points + (long long)pn * 3;
            d0 = q[0] - c[0];
            d1 = q[1] - c[1];
            d2 = q[2] - c[2];
        }

        // ---- L3 mma ----
        float acc3[5][4][4];
#pragma unroll
        for (int im = 0; im < 5; im++)
#pragma unroll
            for (int nq = 0; nq < 4; nq++)
#pragma unroll
                for (int e = 0; e < 4; e++) acc3[im][nq][e] = 0.f;
        const uint4* w3u4 = (const uint4*)(smu + PF_W3F);
        const uint4* h2u4 = (const uint4*)(smu + PF_H2F);
#pragma unroll
        for (int ks = 0; ks < 8; ks++) {
            int base = ((ng * 8 + ks) * 2) * 32 + lane;
            uint4 b01 = w3u4[base];
            uint4 b23 = w3u4[base + 32];
#pragma unroll
            for (int im = 0; im < 5; im++) {
                int mta = mg * 5 + im;
                uint4 A = h2u4[(mta * 8 + ks) * 32 + lane];
                mma16(acc3[im][0], A, b01.x, b01.y);
                mma16(acc3[im][1], A, b01.z, b01.w);
                mma16(acc3[im][2], A, b23.x, b23.y);
                mma16(acc3[im][3], A, b23.z, b23.w);
            }
        }

        // ---- staging + pooled max + feats write ----
        {
            uint32_t* stg = smu + PF_STG + w * 320;
            if (S == 5) {
                float cur = NEGINF;
#pragma unroll
                for (int im = 0; im < 5; im++) {
                    __syncwarp();
#pragma unroll
                    for (int nq = 0; nq < 4; nq++) {
                        uint32_t lo = packbf(acc3[im][nq][0], acc3[im][nq][1]);
                        uint32_t hi = packbf(acc3[im][nq][2], acc3[im][nq][3]);
                        int cs = nq * 4 + (lane & 3);
                        stg[(lane >> 2) * 20 + cs] = lo;
                        stg[((lane >> 2) + 8) * 20 + cs] = hi;
                    }
                    __syncwarp();
#pragma unroll
                    for (int r = 0; r < 16; r++) {
                        uint32_t u = stg[r * 20 + (lane >> 1)];
                        float v = __uint_as_float((lane & 1) ? (u & 0xffff0000u) : (u << 16));
                        cur = fmaxf(cur, v);
                        if (((im * 16 + r + 1) % S) == 0) {
                            int pt = mg * (80 / S) + (im * 16 + r) / S;
                            float val = cur + b3v;
                            float oth = __shfl_xor_sync(0xffffffffu, val, 1);
                            if (!(lane & 1))
                                g_featsb[(size_t)(pt0 + pt) * 384 + SI * 128 + ng * 16 +
                                         (lane >> 1)] = packbf(val, oth);
                            cur = NEGINF;
                        }
                    }
                }
            } else {
                const int cp = lane & 15, rh = lane >> 4;
                uint32_t curp = NEGPK;
#pragma unroll
                for (int im = 0; im < 5; im++) {
                    __syncwarp();
#pragma unroll
                    for (int nq = 0; nq < 4; nq++) {
                        uint32_t lo = packbf(acc3[im][nq][0], acc3[im][nq][1]);
                        uint32_t hi = packbf(acc3[im][nq][2], acc3[im][nq][3]);
                        int cs = nq * 4 + (lane & 3);
                        stg[(lane >> 2) * 20 + cs] = lo;
                        stg[((lane >> 2) + 8) * 20 + cs] = hi;
                    }
                    __syncwarp();
#pragma unroll
                    for (int rr = 0; rr < 8; rr++) {
                        int r = 2 * rr + rh;
                        curp = vmax2(curp, stg[r * 20 + cp]);
                        if (((im * 16 + 2 * rr + 2) % S) == 0) {
                            uint32_t o = __shfl_xor_sync(0xffffffffu, curp, 16);
                            curp = vmax2(curp, o);
                            if (rh == 0) {
                                float lo = __uint_as_float(curp << 16) + b3lo;
                                float hi = __uint_as_float(curp & 0xffff0000u) + b3hi;
                                int grow = im * 16 + 2 * rr + 1;
                                int pt = mg * (80 / S) + grow / S;
                                g_featsb[(size_t)(pt0 + pt) * 384 + SI * 128 + ng * 16 + cp] =
                                    packbf(lo, hi);
                            }
                            curp = NEGPK;
                        }
                    }
                }
            }
        }
        if (pf) {
            sm[PF_NB + t * 4 + 0] = d0;
            sm[PF_NB + t * 4 + 1] = d1;
            sm[PF_NB + t * 4 + 2] = d2;
        }
        __syncthreads();  // B3

        if (tile + nblk < NT) {
#pragma unroll
            for (int ii = 0; ii < 10; ii++) {
                int i = t + ii * 512;
                int dd2 = i & 31, r = i >> 5, d = dd2 * 2;
                float v0 = sm[PF_B1 + d] + sm[PF_NB + r * 4] * sm[PF_W1 + d] +
                           sm[PF_NB + r * 4 + 1] * sm[PF_W1 + 64 + d] +
                           sm[PF_NB + r * 4 + 2] * sm[PF_W1 + 128 + d];
                float v1 = sm[PF_B1 + d + 1] + sm[PF_NB + r * 4] * sm[PF_W1 + d + 1] +
                           sm[PF_NB + r * 4 + 1] * sm[PF_W1 + 64 + d + 1] +
                           sm[PF_NB + r * 4 + 2] * sm[PF_W1 + 128 + d + 1];
                smu[PF_H1F + ((r >> 4) * 4 + (dd2 >> 3)) * 128 + ((r & 7) * 4 + (dd2 & 3)) * 4 +
                    (((r & 8) >> 3) | ((dd2 & 4) >> 1))] = packbf(lrelu(v0), lrelu(v1));
            }
        }
        __syncthreads();  // B4
    }
}

// grid 304 = 2 x 152 SMs (GB300); splits ∝ tile counts (44/87/173)
__global__ void __launch_bounds__(512) patch_all_kernel(
    const float* __restrict__ points, const void* __restrict__ nbr,
    const float* __restrict__ pb1, const float* __restrict__ pb2,
    const float* __restrict__ pb3) {
    extern __shared__ float sm[];
    int b = blockIdx.x;
    if (b < 44)       patch_run<0>(sm, b,       44,  points, nbr, pb1, pb2, pb3);
    else if (b < 131) patch_run<1>(sm, b - 44,  87,  points, nbr, pb1, pb2, pb3);
    else              patch_run<2>(sm, b - 131, 173, points, nbr, pb1, pb2, pb3);
}

// ======================= shared MLP: bf16 mma (R12/R14 proven) =========================
#define MF_A   0
#define MF_H1F 4096
#define MF_H3  4096
#define MF_H4  8256
#define MF_SB1 12288
#define MF_SB2 12544
#define MF_SB3 12672
#define MF_SB4 12736
#define MF_W5  12768
#define MF_W4  12800
#define MF_TOT 14848
#define SMEM_MLP (MF_TOT * 4)

__global__ void __launch_bounds__(256, 2) mlp_kernel(
    const float* __restrict__ sb1, const float* __restrict__ sb2,
    const float* __restrict__ sb3, const float* __restrict__ sb4,
    const float* __restrict__ sw5, const float* __restrict__ sb5,
    float* __restrict__ out) {
    extern __shared__ float sm[];
    uint32_t* smu = (uint32_t*)sm;
    const int t = threadIdx.x;
    const int w = t >> 5, lane = t & 31;
    const int pt0 = blockIdx.x * 64;

    for (int i = t; i < 2048; i += 256) sm[MF_W4 + i] = g_sw4T[i];
    if (t < 256) sm[MF_SB1 + t] = sb1[t];
    if (t < 128) sm[MF_SB2 + t] = sb2[t];
    if (t < 64) sm[MF_SB3 + t] = sb3[t];
    if (t < 32) {
        sm[MF_SB4 + t] = sb4[t];
        sm[MF_W5 + t] = sw5[t];
    }
    __syncthreads();

    float acc1[4][4][4];
#pragma unroll
    for (int mt = 0; mt < 4; mt++)
#pragma unroll
        for (int nt = 0; nt < 4; nt++)
#pragma unroll
            for (int e = 0; e < 4; e++) acc1[mt][nt][e] = 0.f;

    for (int c = 0; c < 6; c++) {
#pragma unroll
        for (int ii = 0; ii < 16; ii++) {
            int i = ii * 256 + t;
            int reg = i & 3, ln = (i >> 2) & 31, ksl = (i >> 7) & 7, mt = i >> 10;
            int row = (ln >> 2) + 8 * (reg & 1);
            int kpair = ksl * 8 + (ln & 3) + 4 * (reg >> 1);
            int p = pt0 + mt * 16 + row;
            if (p >= NPTS) p = NPTS - 1;
            smu[MF_A + i] = g_featsb[(size_t)p * 384 + c * 64 + kpair];
        }
        __syncthreads();
        const uint2* w1b = (const uint2*)g_sw1b;
        const uint4* au4 = (const uint4*)(smu + MF_A);
#pragma unroll
        for (int ksl = 0; ksl < 8; ksl++) {
            uint2 b[4];
#pragma unroll
            for (int nt = 0; nt < 4; nt++)
                b[nt] = w1b[((w * 4 + nt) * 48 + c * 8 + ksl) * 32 + lane];
#pragma unroll
            for (int mt = 0; mt < 4; mt++) {
                uint4 A = au4[(mt * 8 + ksl) * 32 + lane];
#pragma unroll
                for (int nt = 0; nt < 4; nt++) mma16(acc1[mt][nt], A, b[nt].x, b[nt].y);
            }
        }
        __syncthreads();
    }
#pragma unroll
    for (int mt = 0; mt < 4; mt++)
#pragma unroll
        for (int nt = 0; nt < 4; nt++) {
            int n0 = (w * 4 + nt) * 8 + (lane & 3) * 2;
            float be = sm[MF_SB1 + n0], bo = sm[MF_SB1 + n0 + 1];
            uint32_t lo = packbf(lrelu(acc1[mt][nt][0] + be), lrelu(acc1[mt][nt][1] + bo));
            uint32_t hi = packbf(lrelu(acc1[mt][nt][2] + be), lrelu(acc1[mt][nt][3] + bo));
            int kp = (w * 4 + nt) * 4 + (lane & 3);
            int ks = kp >> 3, kpf = kp & 7;
            int lanep = (lane >> 2) * 4 + (kpf & 3);
            int r0 = (kpf & 4) >> 1;
            *(uint2*)(smu + MF_H1F + (mt * 16 + ks) * 128 + lanep * 4 + r0) =
                make_uint2(lo, hi);
        }
    __syncthreads();

    float acc2[4][2][4];
#pragma unroll
    for (int mt = 0; mt < 4; mt++)
#pragma unroll
        for (int j = 0; j < 2; j++)
#pragma unroll
            for (int e = 0; e < 4; e++) acc2[mt][j][e] = 0.f;
    {
        const uint2* w2b = (const uint2*)g_sw2b;
        const uint4* au4 = (const uint4*)(smu + MF_H1F);
#pragma unroll 4
        for (int ks = 0; ks < 16; ks++) {
            uint2 b0 = w2b[(w * 16 + ks) * 32 + lane];
            uint2 b1 = w2b[((w + 8) * 16 + ks) * 32 + lane];
#pragma unroll
            for (int mt = 0; mt < 4; mt++) {
                uint4 A = au4[(mt * 16 + ks) * 32 + lane];
                mma16(acc2[mt][0], A, b0.x, b0.y);
                mma16(acc2[mt][1], A, b1.x, b1.y);
            }
        }
    }
    __syncthreads();
#pragma unroll
    for (int mt = 0; mt < 4; mt++)
#pragma unroll
        for (int j = 0; j < 2; j++) {
            int n0 = (w + j * 8) * 8 + (lane & 3) * 2;
            float be = sm[MF_SB2 + n0], bo = sm[MF_SB2 + n0 + 1];
            uint32_t lo = packbf(lrelu(acc2[mt][j][0] + be), lrelu(acc2[mt][j][1] + bo));
            uint32_t hi = packbf(lrelu(acc2[mt][j][2] + be), lrelu(acc2[mt][j][3] + bo));
            int kp = (w + j * 8) * 4 + (lane & 3);
            int ks = kp >> 3, kpf = kp & 7;
            int lanep = (lane >> 2) * 4 + (kpf & 3);
            int r0 = (kpf & 4) >> 1;
            *(uint2*)(smu + MF_A + (mt * 8 + ks) * 128 + lanep * 4 + r0) = make_uint2(lo, hi);
        }
    __syncthreads();

    float acc3[4][4];
#pragma unroll
    for (int mt = 0; mt < 4; mt++)
#pragma unroll
        for (int e = 0; e < 4; e++) acc3[mt][e] = 0.f;
    {
        const uint2* w3b = (const uint2*)g_sw3b;
        const uint4* au4 = (const uint4*)(smu + MF_A);
#pragma unroll
        for (int ks = 0; ks < 8; ks++) {
            uint2 b = w3b[(w * 8 + ks) * 32 + lane];
#pragma unroll
            for (int mt = 0; mt < 4; mt++) {
                uint4 A = au4[(mt * 8 + ks) * 32 + lane];
                mma16(acc3[mt], A, b.x, b.y);
            }
        }
    }
    __syncthreads();
#pragma unroll
    for (int mt = 0; mt < 4; mt++)
#pragma unroll
        for (int e = 0; e < 4; e++) {
            int m = mt * 16 + (lane >> 2) + ((e >> 1) << 3);
            int n = w * 8 + ((lane & 3) << 1) + (e & 1);
            sm[MF_H3 + m * 65 + n] = lrelu(acc3[mt][e] + sm[MF_SB3 + n]);
        }
    __syncthreads();

#pragma unroll
    for (int ii = 0; ii < 8; ii++) {
        int idx = t + ii * 256;
        int m = idx >> 5, d = idx & 31;
        float a = sm[MF_SB4 + d];
#pragma unroll 8
        for (int k = 0; k < 64; k++) a += sm[MF_H3 + m * 65 + k] * sm[MF_W4 + k * 32 + d];
        sm[MF_H4 + m * 33 + d] = lrelu(a);
    }
    __syncthreads();

    if (t < 64) {
        float s = __ldg(sb5);
#pragma unroll
        for (int k = 0; k < 32; k++) s += sm[MF_H4 + t * 33 + k] * sm[MF_W5 + k];
        int p = pt0 + t;
        if (p < NPTS) out[p] = s;
    }
}

// ======================= launch ========================================================
extern "C" void kernel_launch(void* const* d_in, const int* in_sizes, int n_in,
                              void* d_out, int out_size) {
    (void)out_size;
    const int want[18] = {300000, 2000000, 576, 192, 24576, 384, 98304, 768,
                          196608, 256,    32768, 128, 8192, 64,  2048,  32, 32, 1};
    const void* ptr[18] = {};
    {
        int used[64] = {};
        for (int w = 0; w < 18; w++) {
            for (int i = 0; i < n_in && i < 64; i++) {
                if (!used[i] && in_sizes[i] == want[w]) {
                    ptr[w] = d_in[i];
                    used[i] = 1;
                    break;
                }
            }
        }
        for (int w = 0; w < 18; w++)
            if (!ptr[w] && w < n_in) ptr[w] = d_in[w];
    }

    const float* points = (const float*)ptr[0];
    const void*  nbr    = ptr[1];
    const float* pw1 = (const float*)ptr[2];
    const float* pb1 = (const float*)ptr[3];
    const float* pw2 = (const float*)ptr[4];
    const float* pb2 = (const float*)ptr[5];
    const float* pw3 = (const float*)ptr[6];
    const float* pb3 = (const float*)ptr[7];
    const float* sw1 = (const float*)ptr[8];
    const float* sb1 = (const float*)ptr[9];
    const float* sw2 = (const float*)ptr[10];
    const float* sb2 = (const float*)ptr[11];
    const float* sw3 = (const float*)ptr[12];
    const float* sb3 = (const float*)ptr[13];
    const float* sw4 = (const float*)ptr[14];
    const float* sb4 = (const float*)ptr[15];
    const float* sw5 = (const float*)ptr[16];
    const float* sb5 = (const float*)ptr[17];

    cudaFuncSetAttribute(patch_all_kernel, cudaFuncAttributeMaxDynamicSharedMemorySize,
                         SMEM_PATCH);
    cudaFuncSetAttribute(mlp_kernel, cudaFuncAttributeMaxDynamicSharedMemorySize, SMEM_MLP);

    prep_kernel<<<128, 256>>>(pw1, pw2, pw3, sw1, sw2, sw3, sw4,
                              (const unsigned int*)nbr);
    patch_all_kernel<<<304, 512, SMEM_PATCH>>>(points, nbr, pb1, pb2, pb3);
    mlp_kernel<<<(NPTS + 63) / 64, 256, SMEM_MLP>>>(sb1, sb2, sb3, sb4, sw5, sb5,
                                                    (float*)d_out);
}